// round 2
// baseline (speedup 1.0000x reference)
#include <cuda_runtime.h>
#include <cuda_bf16.h>
#include <math.h>

#define N 8192
#define D 64
#define LAM 0.5f
#define TAU 0.8f
#define INV_TAU 1.25f
#define EPS 1e-8f
#define NTILES 64   // N / 128

// ---------------- device scratch (no allocations allowed) ----------------
__device__ float g_zn_mp[N * D];
__device__ float g_zn_sc[N * D];
__device__ float g_prow_sum[NTILES][N];  // partial over col-tiles, row stats
__device__ float g_prow_pos[NTILES][N];
__device__ float g_pcol_sum[NTILES][N];  // partial over row-tiles, col stats
__device__ float g_pcol_pos[NTILES][N];
__device__ float g_blocksum[32];

// exp(x) for |x| <= ~1.26 : degree-9 Taylor, 9 FMAs, rel err ~1e-5
__device__ __forceinline__ float exp_poly(float x) {
    float p = 2.75573192e-6f;        // 1/9!
    p = fmaf(p, x, 2.48015873e-5f);  // 1/8!
    p = fmaf(p, x, 1.98412698e-4f);  // 1/7!
    p = fmaf(p, x, 1.38888889e-3f);  // 1/6!
    p = fmaf(p, x, 8.33333333e-3f);  // 1/5!
    p = fmaf(p, x, 4.16666667e-2f);  // 1/4!
    p = fmaf(p, x, 1.66666667e-1f);  // 1/3!
    p = fmaf(p, x, 0.5f);
    p = fmaf(p, x, 1.0f);
    p = fmaf(p, x, 1.0f);
    return p;
}

// ---------------- kernel 1: row-normalize both inputs ----------------
// one warp per row; 8 rows / 256-thread block; 2*N rows total
__global__ void normalize_kernel(const float* __restrict__ zmp,
                                 const float* __restrict__ zsc) {
    int gwarp = (blockIdx.x * blockDim.x + threadIdx.x) >> 5;
    int lane = threadIdx.x & 31;
    const float* src;
    float* dst;
    if (gwarp < N) {
        src = zmp + (size_t)gwarp * D;
        dst = g_zn_mp + (size_t)gwarp * D;
    } else {
        src = zsc + (size_t)(gwarp - N) * D;
        dst = g_zn_sc + (size_t)(gwarp - N) * D;
    }
    float v0 = src[lane];
    float v1 = src[lane + 32];
    float s = v0 * v0 + v1 * v1;
#pragma unroll
    for (int off = 16; off > 0; off >>= 1)
        s += __shfl_xor_sync(0xFFFFFFFF, s, off);
    float inv = rsqrtf(s);
    dst[lane] = v0 * inv;
    dst[lane + 32] = v1 * inv;
}

// ---------------- kernel 2: 128x128 tiles, GEMM + exp + pos-weighted reductions ----------------
__global__ __launch_bounds__(256, 2)
void tile_kernel(const int* __restrict__ pos) {
    const int bi = blockIdx.y;   // row tile
    const int bj = blockIdx.x;   // col tile
    const int tx = threadIdx.x;  // 0..15 -> cols
    const int ty = threadIdx.y;  // 0..15 -> rows
    const int tid = ty * 16 + tx;

    // k-major smem tiles, 32-k chunks. Stride 132 keeps float4 alignment.
    __shared__ float As[32][132];
    __shared__ float Bs[32][132];

    const float* Ag = g_zn_mp + (size_t)bi * 128 * D;
    const float* Bg = g_zn_sc + (size_t)bj * 128 * D;

    float acc[8][8];
#pragma unroll
    for (int r = 0; r < 8; r++)
#pragma unroll
        for (int c = 0; c < 8; c++) acc[r][c] = 0.0f;

    const int ty4 = ty * 4, tx4 = tx * 4;

#pragma unroll
    for (int kb = 0; kb < 2; kb++) {
        // load 128 rows x 32 k's for A and B (transposed into smem)
#pragma unroll
        for (int q = 0; q < 4; q++) {
            int l = q * 256 + tid;         // 0..1023 float4 slots
            int row = l >> 3;              // 0..127
            int c4 = l & 7;                // 0..7 -> k offset c4*4
            float4 va = *(const float4*)(Ag + row * D + kb * 32 + c4 * 4);
            float4 vb = *(const float4*)(Bg + row * D + kb * 32 + c4 * 4);
            int k = c4 * 4;
            As[k + 0][row] = va.x; As[k + 1][row] = va.y;
            As[k + 2][row] = va.z; As[k + 3][row] = va.w;
            Bs[k + 0][row] = vb.x; Bs[k + 1][row] = vb.y;
            Bs[k + 2][row] = vb.z; Bs[k + 3][row] = vb.w;
        }
        __syncthreads();

#pragma unroll 8
        for (int k = 0; k < 32; k++) {
            float4 a0 = *(const float4*)&As[k][ty4];
            float4 a1 = *(const float4*)&As[k][64 + ty4];
            float4 b0 = *(const float4*)&Bs[k][tx4];
            float4 b1 = *(const float4*)&Bs[k][64 + tx4];
            float a[8] = {a0.x, a0.y, a0.z, a0.w, a1.x, a1.y, a1.z, a1.w};
            float b[8] = {b0.x, b0.y, b0.z, b0.w, b1.x, b1.y, b1.z, b1.w};
#pragma unroll
            for (int r = 0; r < 8; r++)
#pragma unroll
                for (int c = 0; c < 8; c++)
                    acc[r][c] = fmaf(a[r], b[c], acc[r][c]);
        }
        __syncthreads();
    }

    // exp epilogue (polynomial, avoids MUFU bottleneck)
#pragma unroll
    for (int r = 0; r < 8; r++)
#pragma unroll
        for (int c = 0; c < 8; c++)
            acc[r][c] = exp_poly(acc[r][c] * INV_TAU);

    // local row/col offsets of this thread's 8x8 microtile (4+4 split layout)
    int rol[8], col[8];
#pragma unroll
    for (int r = 0; r < 4; r++) { rol[r] = ty4 + r; rol[r + 4] = 64 + ty4 + r; }
#pragma unroll
    for (int c = 0; c < 4; c++) { col[c] = tx4 + c; col[c + 4] = 64 + tx4 + c; }

    const int rowg0 = bi * 128, colg0 = bj * 128;

    float rp[8], rpp[8], cp[8], cpp[8];
#pragma unroll
    for (int i = 0; i < 8; i++) { rp[i] = 0.f; rpp[i] = 0.f; cp[i] = 0.f; cpp[i] = 0.f; }

    // pos tile (bi,bj): row stats use pos[i][j]
#pragma unroll
    for (int r = 0; r < 8; r++) {
        size_t base = (size_t)(rowg0 + rol[r]) * N + colg0;
        int4 p0 = *(const int4*)(pos + base + tx4);
        int4 p1 = *(const int4*)(pos + base + 64 + tx4);
        int pv[8] = {p0.x, p0.y, p0.z, p0.w, p1.x, p1.y, p1.z, p1.w};
#pragma unroll
        for (int c = 0; c < 8; c++) {
            float ev = acc[r][c];
            rp[r] += ev;
            rpp[r] += pv[c] ? ev : 0.0f;
            cp[c] += ev;
        }
    }
    // pos tile (bj,bi): col stats use pos[j][i] (m_sc2mp = S^T pairs with pos)
#pragma unroll
    for (int c = 0; c < 8; c++) {
        size_t base = (size_t)(colg0 + col[c]) * N + rowg0;
        int4 q0 = *(const int4*)(pos + base + ty4);
        int4 q1 = *(const int4*)(pos + base + 64 + ty4);
        int qv[8] = {q0.x, q0.y, q0.z, q0.w, q1.x, q1.y, q1.z, q1.w};
#pragma unroll
        for (int r = 0; r < 8; r++)
            cpp[c] += qv[r] ? acc[r][c] : 0.0f;
    }

    // in-CTA reductions via smem (reuse As/Bs), deterministic order
    float (*redA)[17] = (float (*)[17])&As[0][0];  // 128*17 floats fits in 32*132
    float (*redB)[17] = (float (*)[17])&Bs[0][0];

    __syncthreads();
    // rows: reduce over tx (16 partials per row)
#pragma unroll
    for (int r = 0; r < 8; r++) { redA[rol[r]][tx] = rp[r]; redB[rol[r]][tx] = rpp[r]; }
    __syncthreads();
    if (tid < 128) {
        float s = 0.f, sp = 0.f;
#pragma unroll
        for (int x = 0; x < 16; x++) { s += redA[tid][x]; sp += redB[tid][x]; }
        g_prow_sum[bj][rowg0 + tid] = s;
        g_prow_pos[bj][rowg0 + tid] = sp;
    }
    __syncthreads();
    // cols: reduce over ty
#pragma unroll
    for (int c = 0; c < 8; c++) { redA[col[c]][ty] = cp[c]; redB[col[c]][ty] = cpp[c]; }
    __syncthreads();
    if (tid < 128) {
        float s = 0.f, sp = 0.f;
#pragma unroll
        for (int x = 0; x < 16; x++) { s += redA[tid][x]; sp += redB[tid][x]; }
        g_pcol_sum[bi][colg0 + tid] = s;
        g_pcol_pos[bi][colg0 + tid] = sp;
    }
}

// ---------------- kernel 3: per-index log terms + block reduction ----------------
__global__ void reduce_kernel() {
    int i = blockIdx.x * 256 + threadIdx.x;  // 0..8191
    float rs = 0.f, rp = 0.f, cs = 0.f, cp = 0.f;
#pragma unroll
    for (int t = 0; t < NTILES; t++) {
        rs += g_prow_sum[t][i];
        rp += g_prow_pos[t][i];
        cs += g_pcol_sum[t][i];
        cp += g_pcol_pos[t][i];
    }
    float contrib = LAM * (logf(rp) - logf(rs + EPS)) +
                    (1.0f - LAM) * (logf(cp) - logf(cs + EPS));

    // block reduce (deterministic tree)
#pragma unroll
    for (int off = 16; off > 0; off >>= 1)
        contrib += __shfl_xor_sync(0xFFFFFFFF, contrib, off);
    __shared__ float ws[8];
    int lane = threadIdx.x & 31, warp = threadIdx.x >> 5;
    if (lane == 0) ws[warp] = contrib;
    __syncthreads();
    if (warp == 0) {
        float v = (lane < 8) ? ws[lane] : 0.0f;
#pragma unroll
        for (int off = 4; off > 0; off >>= 1)
            v += __shfl_xor_sync(0xFFFFFFFF, v, off);
        if (lane == 0) g_blocksum[blockIdx.x] = v;
    }
}

__global__ void final_kernel(float* __restrict__ out) {
    float v = g_blocksum[threadIdx.x];  // 32 blocks in stage 3
#pragma unroll
    for (int off = 16; off > 0; off >>= 1)
        v += __shfl_xor_sync(0xFFFFFFFF, v, off);
    if (threadIdx.x == 0) out[0] = -v * (1.0f / (float)N);
}

// ---------------- launch ----------------
extern "C" void kernel_launch(void* const* d_in, const int* in_sizes, int n_in,
                              void* d_out, int out_size) {
    const float* z_mp = (const float*)d_in[0];
    const float* z_sc = (const float*)d_in[1];
    const int* pos = (const int*)d_in[2];
    float* out = (float*)d_out;

    normalize_kernel<<<2 * N / 8, 256>>>(z_mp, z_sc);
    dim3 grid(NTILES, NTILES), block(16, 16);
    tile_kernel<<<grid, block>>>(pos);
    reduce_kernel<<<N / 256, 256>>>();
    final_kernel<<<1, 32>>>(out);
}

// round 3
// speedup vs baseline: 1.5434x; 1.5434x over previous
#include <cuda_runtime.h>
#include <cuda_bf16.h>
#include <math.h>

#define N 8192
#define D 64
#define LAM 0.5f
#define INV_TAU 1.25f
#define EPS 1e-8f
#define NT 64           // N / 128 tiles
#define NPAIRS 2080     // NT*(NT+1)/2

// ---------------- device scratch ----------------
__device__ float g_zn_mp[N * D];   // tf32-rounded normalized
__device__ float g_zn_sc[N * D];
__device__ float g_prow_sum[NT][N];
__device__ float g_prow_pos[NT][N];
__device__ float g_pcol_sum[NT][N];
__device__ float g_pcol_pos[NT][N];
__device__ float g_blocksum[32];

// exp(x), |x| <= ~1.26 : degree-9 Taylor (FMA pipe, avoids MUFU bottleneck)
__device__ __forceinline__ float exp_poly(float x) {
    float p = 2.75573192e-6f;
    p = fmaf(p, x, 2.48015873e-5f);
    p = fmaf(p, x, 1.98412698e-4f);
    p = fmaf(p, x, 1.38888889e-3f);
    p = fmaf(p, x, 8.33333333e-3f);
    p = fmaf(p, x, 4.16666667e-2f);
    p = fmaf(p, x, 1.66666667e-1f);
    p = fmaf(p, x, 0.5f);
    p = fmaf(p, x, 1.0f);
    p = fmaf(p, x, 1.0f);
    return p;
}

__device__ __forceinline__ void mma_tf32(float* c, const float4& a, const float2& b) {
    const unsigned* A = reinterpret_cast<const unsigned*>(&a);
    const unsigned* B = reinterpret_cast<const unsigned*>(&b);
    asm volatile(
        "mma.sync.aligned.m16n8k8.row.col.f32.tf32.tf32.f32 "
        "{%0,%1,%2,%3}, {%4,%5,%6,%7}, {%8,%9}, {%0,%1,%2,%3};"
        : "+f"(c[0]), "+f"(c[1]), "+f"(c[2]), "+f"(c[3])
        : "r"(A[0]), "r"(A[1]), "r"(A[2]), "r"(A[3]), "r"(B[0]), "r"(B[1]));
}

// ---------------- kernel 1: normalize + round to tf32 ----------------
__global__ void normalize_kernel(const float* __restrict__ zmp,
                                 const float* __restrict__ zsc) {
    int gwarp = (blockIdx.x * blockDim.x + threadIdx.x) >> 5;
    int lane = threadIdx.x & 31;
    const float* src;
    float* dst;
    if (gwarp < N) {
        src = zmp + (size_t)gwarp * D;
        dst = g_zn_mp + (size_t)gwarp * D;
    } else {
        src = zsc + (size_t)(gwarp - N) * D;
        dst = g_zn_sc + (size_t)(gwarp - N) * D;
    }
    float v0 = src[lane];
    float v1 = src[lane + 32];
    float s = v0 * v0 + v1 * v1;
#pragma unroll
    for (int off = 16; off > 0; off >>= 1)
        s += __shfl_xor_sync(0xFFFFFFFF, s, off);
    float inv = rsqrtf(s);
    float o0 = v0 * inv, o1 = v1 * inv;
    unsigned u0, u1;
    asm("cvt.rna.tf32.f32 %0, %1;" : "=r"(u0) : "f"(o0));
    asm("cvt.rna.tf32.f32 %0, %1;" : "=r"(u1) : "f"(o1));
    dst[lane] = __uint_as_float(u0);
    dst[lane + 32] = __uint_as_float(u1);
}

// ---------------- kernel 2: symmetric-pair tile kernel ----------------
// smem layout (dynamic):
//   [0)        Asm  float[8192]  (32 KB)  -- permuted A fragments (also red overlay)
//   [32K)      Bsm  float[8192]  (32 KB)
//   [64K)      P    bytes 128x132 (pos(b0,b1))
//   [64K+16896)Q    bytes 128x132 (pos(b1,b0))
#define SMEM_BYTES (32768 + 32768 + 16896 + 16896)

__global__ __launch_bounds__(256, 2)
void pair_kernel(const int* __restrict__ pos) {
    extern __shared__ char smem[];
    float* Asm = (float*)smem;
    float* Bsm = (float*)(smem + 32768);
    unsigned char* Pb = (unsigned char*)(smem + 65536);
    unsigned char* Qb = (unsigned char*)(smem + 65536 + 16896);
    // reduction overlay (on Asm, after all frag reads complete)
    float* RedRowS = Asm;            // [128][4]
    float* RedRowP = Asm + 512;      // [128][4]
    float* RedColS = Asm + 1024;     // [128][2]
    float* RedColP = Asm + 1280;     // [128][2]

    const int tid = threadIdx.x;
    const int lane = tid & 31;
    const int wid = tid >> 5;
    const int wm = wid >> 2;   // 0..1 : 64-row slab
    const int wn = wid & 3;    // 0..3 : 32-col slab
    const int q = lane >> 2, l4 = lane & 3;

    // triangular decode: blockIdx.x -> (b0, b1), b0 <= b1
    int b0 = 0, rem = blockIdx.x;
    while (rem >= NT - b0) { rem -= NT - b0; b0++; }
    int b1 = b0 + rem;

    // ---- stage pos tiles as bytes (each global pos element read exactly once) ----
    {
        const int* P0 = pos + (size_t)(b0 * 128) * N + b1 * 128;
        const int* Q0 = pos + (size_t)(b1 * 128) * N + b0 * 128;
#pragma unroll
        for (int i = 0; i < 16; i++) {
            int idx = tid + i * 256;          // 0..4095 int4 slots
            int r = idx >> 5;                 // row 0..127
            int c4 = idx & 31;                // int4 within row
            int4 p = *(const int4*)(P0 + (size_t)r * N + c4 * 4);
            unsigned pb = (p.x & 1) | ((p.y & 1) << 8) | ((p.z & 1) << 16) | ((p.w & 1) << 24);
            *(unsigned*)(Pb + r * 132 + c4 * 4) = pb;
            int4 qq = *(const int4*)(Q0 + (size_t)r * N + c4 * 4);
            unsigned qb = (qq.x & 1) | ((qq.y & 1) << 8) | ((qq.z & 1) << 16) | ((qq.w & 1) << 24);
            *(unsigned*)(Qb + r * 132 + c4 * 4) = qb;
        }
    }

    const int nphase = (b0 == b1) ? 1 : 2;

    for (int t = 0; t < nphase; t++) {
        const int rb = t ? b1 : b0;   // row tile (mp side)
        const int cb = t ? b0 : b1;   // col tile (sc side)
        const int RG = rb * 128, CG = cb * 128;

        __syncthreads();   // smem (Asm/Bsm/red) free for restage

        // ---- stage z tiles into permuted fragment layout ----
        const float* Azg = g_zn_mp + (size_t)RG * D;
        const float* Bzg = g_zn_sc + (size_t)CG * D;
#pragma unroll
        for (int i = 0; i < 8; i++) {
            int idx = tid + i * 256;       // 0..2047 float4 slots
            int m = idx >> 4;              // row 0..127
            int c = idx & 15;              // float4 col (k = 4c..4c+3)
            int ks = c >> 1, khi = c & 1;
            {
                float4 v = *(const float4*)(Azg + m * D + c * 4);
                int reg = (((m & 15) >= 8) ? 1 : 0) + 2 * khi;
                float* base = Asm + (((ks * 8 + (m >> 4)) * 32) + (m & 7) * 4) * 4 + reg;
                base[0] = v.x; base[4] = v.y; base[8] = v.z; base[12] = v.w;
            }
            {
                float4 v = *(const float4*)(Bzg + m * D + c * 4);
                int reg = khi;
                float* base = Bsm + (((ks * 16 + (m >> 3)) * 32) + (m & 7) * 4) * 2 + reg;
                base[0] = v.x; base[2] = v.y; base[4] = v.z; base[6] = v.w;
            }
        }
        __syncthreads();

        // ---- tensor-core mainloop: warp tile 64x32 (4 m-tiles x 4 n-tiles) ----
        float acc[4][4][4];
#pragma unroll
        for (int mt = 0; mt < 4; mt++)
#pragma unroll
            for (int nt = 0; nt < 4; nt++)
#pragma unroll
                for (int r = 0; r < 4; r++) acc[mt][nt][r] = 0.0f;

#pragma unroll
        for (int ks = 0; ks < 8; ks++) {
            float4 a[4];
            float2 b[4];
#pragma unroll
            for (int mt = 0; mt < 4; mt++)
                a[mt] = *(const float4*)(Asm + ((ks * 8 + wm * 4 + mt) * 32 + lane) * 4);
#pragma unroll
            for (int nt = 0; nt < 4; nt++)
                b[nt] = *(const float2*)(Bsm + ((ks * 16 + wn * 4 + nt) * 32 + lane) * 2);
#pragma unroll
            for (int mt = 0; mt < 4; mt++)
#pragma unroll
                for (int nt = 0; nt < 4; nt++)
                    mma_tf32(acc[mt][nt], a[mt], b[nt]);
        }

        // ---- epilogue: exp + pos pairing + partial reductions ----
        const unsigned char* rowPos = t ? Qb : Pb;   // pos(tile_row, tile_col)
        const unsigned char* colPos = t ? Pb : Qb;   // pos(tile_col, tile_row), [c][r]

        float rs[8], rp2[8];
        float cs[4][2], cp2[4][2];
#pragma unroll
        for (int nt = 0; nt < 4; nt++) { cs[nt][0] = cs[nt][1] = 0.f; cp2[nt][0] = cp2[nt][1] = 0.f; }

#pragma unroll
        for (int mt = 0; mt < 4; mt++) {
#pragma unroll
            for (int half = 0; half < 2; half++) {
                int r = wm * 64 + mt * 16 + q + 8 * half;   // local row in 128-tile
                float rsum = 0.f, rpos = 0.f;
#pragma unroll
                for (int nt = 0; nt < 4; nt++) {
                    int c0 = wn * 32 + nt * 8 + 2 * l4;
                    float v0 = exp_poly(acc[mt][nt][half * 2 + 0] * INV_TAU);
                    float v1 = exp_poly(acc[mt][nt][half * 2 + 1] * INV_TAU);
                    unsigned char pw0 = rowPos[r * 132 + c0];
                    unsigned char pw1 = rowPos[r * 132 + c0 + 1];
                    rsum += v0 + v1;
                    if (pw0) rpos += v0;
                    if (pw1) rpos += v1;
                    cs[nt][0] += v0;
                    cs[nt][1] += v1;
                    unsigned char q0 = colPos[c0 * 132 + r];
                    unsigned char q1 = colPos[(c0 + 1) * 132 + r];
                    if (q0) cp2[nt][0] += v0;
                    if (q1) cp2[nt][1] += v1;
                }
                // quad reduce (over l4 = cols within quad)
                rsum += __shfl_xor_sync(0xFFFFFFFF, rsum, 1);
                rsum += __shfl_xor_sync(0xFFFFFFFF, rsum, 2);
                rpos += __shfl_xor_sync(0xFFFFFFFF, rpos, 1);
                rpos += __shfl_xor_sync(0xFFFFFFFF, rpos, 2);
                rs[mt * 2 + half] = rsum;
                rp2[mt * 2 + half] = rpos;
            }
        }
        // col reduce over q (rows within warp)
#pragma unroll
        for (int nt = 0; nt < 4; nt++)
#pragma unroll
            for (int p = 0; p < 2; p++) {
                float v = cs[nt][p];
                v += __shfl_xor_sync(0xFFFFFFFF, v, 4);
                v += __shfl_xor_sync(0xFFFFFFFF, v, 8);
                v += __shfl_xor_sync(0xFFFFFFFF, v, 16);
                cs[nt][p] = v;
                float w = cp2[nt][p];
                w += __shfl_xor_sync(0xFFFFFFFF, w, 4);
                w += __shfl_xor_sync(0xFFFFFFFF, w, 8);
                w += __shfl_xor_sync(0xFFFFFFFF, w, 16);
                cp2[nt][p] = w;
            }

        __syncthreads();   // Asm frag reads done by all warps -> safe to overlay

        if (l4 == 0) {
#pragma unroll
            for (int mt = 0; mt < 4; mt++)
#pragma unroll
                for (int half = 0; half < 2; half++) {
                    int r = wm * 64 + mt * 16 + q + 8 * half;
                    RedRowS[r * 4 + wn] = rs[mt * 2 + half];
                    RedRowP[r * 4 + wn] = rp2[mt * 2 + half];
                }
        }
        if (lane < 4) {
#pragma unroll
            for (int nt = 0; nt < 4; nt++)
#pragma unroll
                for (int p = 0; p < 2; p++) {
                    int c = wn * 32 + nt * 8 + 2 * lane + p;
                    RedColS[c * 2 + wm] = cs[nt][p];
                    RedColP[c * 2 + wm] = cp2[nt][p];
                }
        }
        __syncthreads();

        if (tid < 128) {
            float s = RedRowS[tid * 4 + 0] + RedRowS[tid * 4 + 1] +
                      RedRowS[tid * 4 + 2] + RedRowS[tid * 4 + 3];
            float sp = RedRowP[tid * 4 + 0] + RedRowP[tid * 4 + 1] +
                       RedRowP[tid * 4 + 2] + RedRowP[tid * 4 + 3];
            g_prow_sum[cb][RG + tid] = s;
            g_prow_pos[cb][RG + tid] = sp;
            float c = RedColS[tid * 2 + 0] + RedColS[tid * 2 + 1];
            float cp = RedColP[tid * 2 + 0] + RedColP[tid * 2 + 1];
            g_pcol_sum[rb][CG + tid] = c;
            g_pcol_pos[rb][CG + tid] = cp;
        }
    }
}

// ---------------- kernel 3: per-index log terms + block reduction ----------------
__global__ void reduce_kernel() {
    int i = blockIdx.x * 256 + threadIdx.x;
    float rs = 0.f, rp = 0.f, cs = 0.f, cp = 0.f;
#pragma unroll
    for (int t = 0; t < NT; t++) {
        rs += g_prow_sum[t][i];
        rp += g_prow_pos[t][i];
        cs += g_pcol_sum[t][i];
        cp += g_pcol_pos[t][i];
    }
    float contrib = LAM * (logf(rp) - logf(rs + EPS)) +
                    (1.0f - LAM) * (logf(cp) - logf(cs + EPS));
#pragma unroll
    for (int off = 16; off > 0; off >>= 1)
        contrib += __shfl_xor_sync(0xFFFFFFFF, contrib, off);
    __shared__ float ws[8];
    int lane = threadIdx.x & 31, warp = threadIdx.x >> 5;
    if (lane == 0) ws[warp] = contrib;
    __syncthreads();
    if (warp == 0) {
        float v = (lane < 8) ? ws[lane] : 0.0f;
#pragma unroll
        for (int off = 4; off > 0; off >>= 1)
            v += __shfl_xor_sync(0xFFFFFFFF, v, off);
        if (lane == 0) g_blocksum[blockIdx.x] = v;
    }
}

__global__ void final_kernel(float* __restrict__ out) {
    float v = g_blocksum[threadIdx.x];
#pragma unroll
    for (int off = 16; off > 0; off >>= 1)
        v += __shfl_xor_sync(0xFFFFFFFF, v, off);
    if (threadIdx.x == 0) out[0] = -v * (1.0f / (float)N);
}

// ---------------- launch ----------------
extern "C" void kernel_launch(void* const* d_in, const int* in_sizes, int n_in,
                              void* d_out, int out_size) {
    const float* z_mp = (const float*)d_in[0];
    const float* z_sc = (const float*)d_in[1];
    const int* pos = (const int*)d_in[2];
    float* out = (float*)d_out;

    cudaFuncSetAttribute(pair_kernel, cudaFuncAttributeMaxDynamicSharedMemorySize,
                         SMEM_BYTES);

    normalize_kernel<<<2 * N / 8, 256>>>(z_mp, z_sc);
    pair_kernel<<<NPAIRS, 256, SMEM_BYTES>>>(pos);
    reduce_kernel<<<N / 256, 256>>>();
    final_kernel<<<1, 32>>>(out);
}